// round 3
// baseline (speedup 1.0000x reference)
#include <cuda_runtime.h>
#include <cuda_bf16.h>

// PMF: out[p] = relu(dot(user_emb[user_ids[p]], item_emb[item_ids[p]])), D=64 fp32.
//
// R3: software-pipelined id prefetch. 16 lanes per pair (one float4 per lane,
// two coalesced 128B lines per 256B row). Each group handles PB=4 pairs per
// tile; each block runs TILES=8 tiles back-to-back, prefetching the next
// tile's ids while the current tile's row loads are in flight. This hides the
// dependent id-load latency that capped R2 at 60% DRAM.

#define HIDDEN 64
#define THREADS 256
#define GROUPS_PER_BLOCK (THREADS / 16)            // 16
#define PB 4                                        // pairs per group per tile
#define TILE_PAIRS (GROUPS_PER_BLOCK * PB)          // 64
#define TILES 8
#define PAIRS_PER_BLOCK (TILE_PAIRS * TILES)        // 512

__global__ __launch_bounds__(THREADS)
void pmf_kernel(const float* __restrict__ user_emb,
                const float* __restrict__ item_emb,
                const int*   __restrict__ user_ids,
                const int*   __restrict__ item_ids,
                float*       __restrict__ out,
                int num_pairs)
{
    const int group = threadIdx.x >> 4;    // 0..15
    const int lane  = threadIdx.x & 15;    // 0..15
    const int block_base = blockIdx.x * PAIRS_PER_BLOCK;

    int uid[PB], iid[PB];

    // Prologue: prefetch ids for tile 0.
    #pragma unroll
    for (int k = 0; k < PB; k++) {
        int p = block_base + k * GROUPS_PER_BLOCK + group;
        int q = (p < num_pairs) ? p : 0;
        uid[k] = __ldg(&user_ids[q]);
        iid[k] = __ldg(&item_ids[q]);
    }

    #pragma unroll
    for (int t = 0; t < TILES; t++) {
        const int tile_base = block_base + t * TILE_PAIRS;

        // Phase A: issue all row loads for tile t (MLP = 8 per thread).
        float4 u[PB], v[PB];
        #pragma unroll
        for (int k = 0; k < PB; k++) {
            u[k] = __ldg(reinterpret_cast<const float4*>(
                       user_emb + (long long)uid[k] * HIDDEN) + lane);
            v[k] = __ldg(reinterpret_cast<const float4*>(
                       item_emb + (long long)iid[k] * HIDDEN) + lane);
        }

        // Phase B: prefetch ids for tile t+1 while row loads are in flight.
        if (t + 1 < TILES) {
            #pragma unroll
            for (int k = 0; k < PB; k++) {
                int p = tile_base + TILE_PAIRS + k * GROUPS_PER_BLOCK + group;
                int q = (p < num_pairs) ? p : 0;
                uid[k] = __ldg(&user_ids[q]);
                iid[k] = __ldg(&item_ids[q]);
            }
        }

        // Phase C: consume row loads, reduce, store.
        #pragma unroll
        for (int k = 0; k < PB; k++) {
            float acc = u[k].x * v[k].x + u[k].y * v[k].y
                      + u[k].z * v[k].z + u[k].w * v[k].w;
            acc += __shfl_xor_sync(0xFFFFFFFFu, acc, 8);
            acc += __shfl_xor_sync(0xFFFFFFFFu, acc, 4);
            acc += __shfl_xor_sync(0xFFFFFFFFu, acc, 2);
            acc += __shfl_xor_sync(0xFFFFFFFFu, acc, 1);
            int p = tile_base + k * GROUPS_PER_BLOCK + group;
            if (lane == 0 && p < num_pairs)
                out[p] = fmaxf(acc, 0.0f);
        }
    }
}

extern "C" void kernel_launch(void* const* d_in, const int* in_sizes, int n_in,
                              void* d_out, int out_size)
{
    const float* user_emb = (const float*)d_in[0];
    const float* item_emb = (const float*)d_in[1];
    const int*   user_ids = (const int*)d_in[2];
    const int*   item_ids = (const int*)d_in[3];
    float*       out      = (float*)d_out;

    int num_pairs = in_sizes[2];
    int blocks = (num_pairs + PAIRS_PER_BLOCK - 1) / PAIRS_PER_BLOCK;

    pmf_kernel<<<blocks, THREADS>>>(user_emb, item_emb, user_ids, item_ids,
                                    out, num_pairs);
}

// round 4
// speedup vs baseline: 1.4702x; 1.4702x over previous
#include <cuda_runtime.h>
#include <cuda_bf16.h>

// PMF: out[p] = relu(dot(user_emb[user_ids[p]], item_emb[item_ids[p]])), D=64 fp32.
//
// R4: revert R3's tile loop (it serialized tiles within a warp and regressed).
// Back to the flat R2 structure, but PB=8 pairs per 16-lane group:
//   phase 1: 16 independent id loads
//   phase 2: 16 independent float4 row loads (256B in flight per thread)
//   phase 3: 8 dot-products + 16-lane shfl reductions + stores
// Warps retire after one shot; latency hiding comes from intra-thread MLP x
// warp concurrency. launch_bounds(256,3) caps regs (~84) to avoid spill.

#define HIDDEN 64
#define THREADS 256
#define GROUPS_PER_BLOCK (THREADS / 16)            // 16
#define PB 8                                        // pairs per group
#define PAIRS_PER_BLOCK (GROUPS_PER_BLOCK * PB)     // 128

__global__ __launch_bounds__(THREADS, 3)
void pmf_kernel(const float* __restrict__ user_emb,
                const float* __restrict__ item_emb,
                const int*   __restrict__ user_ids,
                const int*   __restrict__ item_ids,
                float*       __restrict__ out,
                int num_pairs)
{
    const int group = threadIdx.x >> 4;    // 0..15
    const int lane  = threadIdx.x & 15;    // 0..15
    const int base  = blockIdx.x * PAIRS_PER_BLOCK + group;

    // Phase 1: all id loads, independent, front-batched.
    int uid[PB], iid[PB];
    #pragma unroll
    for (int k = 0; k < PB; k++) {
        int p = base + k * GROUPS_PER_BLOCK;
        int q = (p < num_pairs) ? p : 0;
        uid[k] = __ldg(&user_ids[q]);
        iid[k] = __ldg(&item_ids[q]);
    }

    // Phase 2: all row loads, independent, front-batched (16 LDG.128/thread).
    float4 u[PB], v[PB];
    #pragma unroll
    for (int k = 0; k < PB; k++) {
        u[k] = __ldg(reinterpret_cast<const float4*>(
                   user_emb + (long long)uid[k] * HIDDEN) + lane);
        v[k] = __ldg(reinterpret_cast<const float4*>(
                   item_emb + (long long)iid[k] * HIDDEN) + lane);
    }

    // Phase 3: dot products, 16-lane reductions, stores.
    #pragma unroll
    for (int k = 0; k < PB; k++) {
        float acc = u[k].x * v[k].x + u[k].y * v[k].y
                  + u[k].z * v[k].z + u[k].w * v[k].w;
        acc += __shfl_xor_sync(0xFFFFFFFFu, acc, 8);
        acc += __shfl_xor_sync(0xFFFFFFFFu, acc, 4);
        acc += __shfl_xor_sync(0xFFFFFFFFu, acc, 2);
        acc += __shfl_xor_sync(0xFFFFFFFFu, acc, 1);
        int p = base + k * GROUPS_PER_BLOCK;
        if (lane == 0 && p < num_pairs)
            out[p] = fmaxf(acc, 0.0f);
    }
}

extern "C" void kernel_launch(void* const* d_in, const int* in_sizes, int n_in,
                              void* d_out, int out_size)
{
    const float* user_emb = (const float*)d_in[0];
    const float* item_emb = (const float*)d_in[1];
    const int*   user_ids = (const int*)d_in[2];
    const int*   item_ids = (const int*)d_in[3];
    float*       out      = (float*)d_out;

    int num_pairs = in_sizes[2];
    int blocks = (num_pairs + PAIRS_PER_BLOCK - 1) / PAIRS_PER_BLOCK;

    pmf_kernel<<<blocks, THREADS>>>(user_emb, item_emb, user_ids, item_ids,
                                    out, num_pairs);
}